// round 15
// baseline (speedup 1.0000x reference)
#include <cuda_runtime.h>
#include <cuda_bf16.h>
#include <math.h>
#include <stdint.h>

// Shapes (fixed)
#define BATCH 8
#define CDIM 512
#define HWDIM 4096
#define CPG 16
#define EPSV 1e-6f

// GEMM tiling: 128x128 CTA tile, BK=64 bf16 (128B rows), 3-stage cp.async
#define TM 128
#define TN 128
#define BK 64
#define TILE_BYTES (TM * 128)           // 16KB per operand stage
#define STG_BYTES (2 * TILE_BYTES)      // 32KB
#define NSTAGE 3
#define SMEM_DYN (NSTAGE * STG_BYTES)   // 96KB
#define GN_SMEM (CPG * HWDIM * 2)       // 128KB bf16 cache

typedef __nv_bfloat16 bf16;
typedef __nv_bfloat162 bf162;

// ---------------- scratch (device globals) ---------------------------------
__device__ bf16  g_xnb [(size_t)BATCH * HWDIM * CDIM];     // 32MB GN out [B,N,C]
__device__ bf16  g_qkb [(size_t)2 * BATCH * HWDIM * CDIM]; // 64MB Q,K planes
__device__ bf16  g_vtb [(size_t)BATCH * HWDIM * CDIM];     // 32MB V^T [B,C,N]
__device__ bf16  g_sb  [(size_t)BATCH * HWDIM * HWDIM];    // 256MB exp-scores bf16
__device__ bf16  g_attnb[(size_t)BATCH * HWDIM * CDIM];    // 32MB P@V out
__device__ bf16  g_wb  [4 * CDIM * CDIM];                  // 2MB bf16 weights
__device__ float g_biasp[3 * CDIM];                        // packed biases q,k,v
__device__ float g_rowsum[BATCH * HWDIM];                  // softmax denominators

// ---------------- PTX helpers ----------------------------------------------
__device__ __forceinline__ uint32_t smem_u32(const void* p) {
    uint32_t a;
    asm("{ .reg .u64 t; cvta.to.shared.u64 t, %1; cvt.u32.u64 %0, t; }"
        : "=r"(a) : "l"(p));
    return a;
}

__device__ __forceinline__ void ldsm4(uint32_t* r, uint32_t addr) {
    asm volatile("ldmatrix.sync.aligned.m8n8.x4.shared.b16 {%0,%1,%2,%3}, [%4];"
                 : "=r"(r[0]), "=r"(r[1]), "=r"(r[2]), "=r"(r[3]) : "r"(addr));
}

__device__ __forceinline__ void mma_bf16(float* c, const uint32_t* a,
                                         uint32_t b0, uint32_t b1) {
    asm volatile(
        "mma.sync.aligned.m16n8k16.row.col.f32.bf16.bf16.f32 "
        "{%0,%1,%2,%3}, {%4,%5,%6,%7}, {%8,%9}, {%0,%1,%2,%3};"
        : "+f"(c[0]), "+f"(c[1]), "+f"(c[2]), "+f"(c[3])
        : "r"(a[0]), "r"(a[1]), "r"(a[2]), "r"(a[3]), "r"(b0), "r"(b1));
}

__device__ __forceinline__ void cp16(uint32_t dst, const void* src) {
    asm volatile("cp.async.cg.shared.global [%0], [%1], 16;" :: "r"(dst), "l"(src));
}
#define CP_COMMIT() asm volatile("cp.async.commit_group;" ::: "memory")
#define CP_WAIT1()  asm volatile("cp.async.wait_group 1;" ::: "memory")

// ---------------- bf16 GEMM NT: C = alpha * A @ B^T (+ bias) ----------------
// A: [M,K] lda, B: [N,K] ldb bf16 K-major.
// mode 0: f32 C row-major
// mode 1: bf16 C row-major (per-z plane sC; bias per-z plane sBias, col-index)
// mode 2: fused residual + transpose -> f32 [B,C,H,W]
// mode 3: V^T planes: C[(n>>12)*HW*C + m*HW + (n&4095)], bias row-indexed
// mode 5: S-GEMM: store bf16(exp(acc*alpha)); accumulate row sums -> rsumg
// mode 6: PV: bf16 out scaled by 1/rsumg[z*HW + m]
__global__ __launch_bounds__(256, 2) void gemm_bf16(const bf16* __restrict__ A,
                                                    const bf16* __restrict__ B,
                                                    const float* __restrict__ bias,
                                                    void* __restrict__ Cv,
                                                    const float* __restrict__ xres,
                                                    float* __restrict__ rsumg,
                                                    int K, int lda, int ldb, int ldc,
                                                    float alpha, int mode,
                                                    size_t sA, size_t sB, size_t sC,
                                                    int sBias) {
    extern __shared__ char dsm[];
    uint32_t smem_base = smem_u32(dsm);

    A += (size_t)blockIdx.z * sA;
    B += (size_t)blockIdx.z * sB;
    if (bias) bias += (size_t)blockIdx.z * sBias;
    int bm = blockIdx.y * TM, bn = blockIdx.x * TN;
    int tid = threadIdx.x, wid = tid >> 5, lane = tid & 31;
    int wm = (wid & 1) * 64, wn = (wid >> 1) * 32;

    int lrow = tid >> 1;
    int g0 = (tid & 1) * 4;
    const bf16* ag = A + (size_t)(bm + lrow) * lda + g0 * 8;
    const bf16* bg = B + (size_t)(bn + lrow) * ldb + g0 * 8;
    int rx = lrow & 7;
    uint32_t sAoff[4], sBoff[4];
    #pragma unroll
    for (int j = 0; j < 4; j++) {
        uint32_t o = (uint32_t)lrow * 128 + (uint32_t)(((g0 + j) ^ rx) << 4);
        sAoff[j] = o;
        sBoff[j] = TILE_BYTES + o;
    }

    int arl = (lane & 7) + ((lane >> 3) & 1) * 8;
    int ahi = lane >> 4;
    uint32_t a_rowoff[4]; int a_rx[4];
    #pragma unroll
    for (int mf = 0; mf < 4; mf++) {
        int row = wm + mf * 16 + arl;
        a_rowoff[mf] = (uint32_t)row * 128;
        a_rx[mf] = row & 7;
    }
    int brl = (lane & 7) + ((lane >> 4) & 1) * 8;
    int bhi = (lane >> 3) & 1;
    uint32_t b_rowoff[2]; int b_rx[2];
    #pragma unroll
    for (int ng = 0; ng < 2; ng++) {
        int row = wn + ng * 16 + brl;
        b_rowoff[ng] = TILE_BYTES + (uint32_t)row * 128;
        b_rx[ng] = row & 7;
    }

    const int NC = K / BK;

    #pragma unroll
    for (int c = 0; c < 2; c++) {
        uint32_t st = smem_base + c * STG_BYTES;
        const bf16* a0 = ag + c * BK;
        const bf16* b0 = bg + c * BK;
        #pragma unroll
        for (int j = 0; j < 4; j++) cp16(st + sAoff[j], a0 + j * 8);
        #pragma unroll
        for (int j = 0; j < 4; j++) cp16(st + sBoff[j], b0 + j * 8);
        CP_COMMIT();
    }

    float acc[4][4][4];
    #pragma unroll
    for (int i = 0; i < 4; i++)
        #pragma unroll
        for (int j = 0; j < 4; j++)
            #pragma unroll
            for (int r = 0; r < 4; r++) acc[i][j][r] = 0.f;

    for (int c = 0; c < NC; c++) {
        int buf = c % NSTAGE;
        CP_WAIT1();
        __syncthreads();
        if (c + 2 < NC) {
            uint32_t st = smem_base + ((c + 2) % NSTAGE) * STG_BYTES;
            const bf16* a0 = ag + (c + 2) * BK;
            const bf16* b0 = bg + (c + 2) * BK;
            #pragma unroll
            for (int j = 0; j < 4; j++) cp16(st + sAoff[j], a0 + j * 8);
            #pragma unroll
            for (int j = 0; j < 4; j++) cp16(st + sBoff[j], b0 + j * 8);
        }
        CP_COMMIT();

        uint32_t base = smem_base + buf * STG_BYTES;
        #pragma unroll
        for (int kf = 0; kf < 4; kf++) {
            uint32_t a[4][4], b[2][4];
            #pragma unroll
            for (int mf = 0; mf < 4; mf++)
                ldsm4(a[mf], base + a_rowoff[mf] +
                      (uint32_t)(((((kf << 1) | ahi)) ^ a_rx[mf]) << 4));
            #pragma unroll
            for (int ng = 0; ng < 2; ng++)
                ldsm4(b[ng], base + b_rowoff[ng] +
                      (uint32_t)(((((kf << 1) | bhi)) ^ b_rx[ng]) << 4));
            #pragma unroll
            for (int mf = 0; mf < 4; mf++)
                #pragma unroll
                for (int ng = 0; ng < 2; ng++) {
                    mma_bf16(acc[mf][ng * 2 + 0], a[mf], b[ng][0], b[ng][1]);
                    mma_bf16(acc[mf][ng * 2 + 1], a[mf], b[ng][2], b[ng][3]);
                }
        }
    }
    __syncthreads();

    // ---- epilogue ----
    float* rs = (float*)dsm;             // smem reused for row sums (mode 5)
    if (mode == 5) {
        if (tid < TM) rs[tid] = 0.f;
        __syncthreads();
    }

    int r4 = lane >> 2, c2 = (lane & 3) * 2;
    #pragma unroll
    for (int mf = 0; mf < 4; mf++) {
        int lr = wm + mf * 16 + r4;          // local row in tile
        int m0 = bm + lr;
        float inv0 = 1.f, inv1 = 1.f;
        if (mode == 6) {
            inv0 = 1.f / rsumg[(size_t)blockIdx.z * HWDIM + m0];
            inv1 = 1.f / rsumg[(size_t)blockIdx.z * HWDIM + m0 + 8];
        }
        float p0 = 0.f, p1 = 0.f;            // row-sum partials (mode 5)
        #pragma unroll
        for (int nf = 0; nf < 4; nf++) {
            int n0 = bn + wn + (nf >> 1) * 16 + (nf & 1) * 8 + c2;
            float bx = 0.f, by = 0.f;
            if (bias && mode != 3) { bx = bias[n0]; by = bias[n0 + 1]; }
            float* ac = acc[mf][nf];
            float x0 = ac[0] * alpha + bx, y0 = ac[1] * alpha + by;
            float x1 = ac[2] * alpha + bx, y1 = ac[3] * alpha + by;
            if (mode == 1) {
                bf16* C = (bf16*)Cv + blockIdx.z * sC;
                bf162 h0 = __floats2bfloat162_rn(x0, y0);
                bf162 h1 = __floats2bfloat162_rn(x1, y1);
                *(bf162*)(C + (size_t)m0 * ldc + n0) = h0;
                *(bf162*)(C + (size_t)(m0 + 8) * ldc + n0) = h1;
            } else if (mode == 5) {
                x0 = __expf(x0); y0 = __expf(y0);
                x1 = __expf(x1); y1 = __expf(y1);
                p0 += x0 + y0;  p1 += x1 + y1;
                bf16* C = (bf16*)Cv + blockIdx.z * sC;
                bf162 h0 = __floats2bfloat162_rn(x0, y0);
                bf162 h1 = __floats2bfloat162_rn(x1, y1);
                *(bf162*)(C + (size_t)m0 * ldc + n0) = h0;
                *(bf162*)(C + (size_t)(m0 + 8) * ldc + n0) = h1;
            } else if (mode == 6) {
                bf16* C = (bf16*)Cv + blockIdx.z * sC;
                bf162 h0 = __floats2bfloat162_rn(x0 * inv0, y0 * inv0);
                bf162 h1 = __floats2bfloat162_rn(x1 * inv1, y1 * inv1);
                *(bf162*)(C + (size_t)m0 * ldc + n0) = h0;
                *(bf162*)(C + (size_t)(m0 + 8) * ldc + n0) = h1;
            } else if (mode == 0) {
                float* C = (float*)Cv + blockIdx.z * sC;
                *(float2*)(C + (size_t)m0 * ldc + n0) = make_float2(x0, y0);
                *(float2*)(C + (size_t)(m0 + 8) * ldc + n0) = make_float2(x1, y1);
            } else if (mode == 2) {
                float* C = (float*)Cv;
                int m1 = m0 + 8;
                size_t i00 = (((size_t)(m0 >> 12) * CDIM) + n0) * HWDIM + (m0 & 4095);
                size_t i01 = (((size_t)(m0 >> 12) * CDIM) + n0 + 1) * HWDIM + (m0 & 4095);
                size_t i10 = (((size_t)(m1 >> 12) * CDIM) + n0) * HWDIM + (m1 & 4095);
                size_t i11 = (((size_t)(m1 >> 12) * CDIM) + n0 + 1) * HWDIM + (m1 & 4095);
                C[i00] = x0 + xres[i00];
                C[i01] = y0 + xres[i01];
                C[i10] = x1 + xres[i10];
                C[i11] = y1 + xres[i11];
            } else {
                // mode 3: V^T planes; m = channel, n = global token; bias by row
                bf16* C = (bf16*)Cv;
                float b0f = bias ? bias[m0] : 0.f;
                float b1f = bias ? bias[m0 + 8] : 0.f;
                bf162 h0 = __floats2bfloat162_rn(x0 + b0f, y0 + b0f);
                bf162 h1 = __floats2bfloat162_rn(x1 + b1f, y1 + b1f);
                size_t plane = (size_t)(n0 >> 12) * ((size_t)HWDIM * CDIM);
                int nt = n0 & 4095;
                *(bf162*)(C + plane + (size_t)m0 * HWDIM + nt) = h0;
                *(bf162*)(C + plane + (size_t)(m0 + 8) * HWDIM + nt) = h1;
            }
        }
        if (mode == 5) {
            atomicAdd(&rs[lr], p0);
            atomicAdd(&rs[lr + 8], p1);
        }
    }
    if (mode == 5) {
        __syncthreads();
        if (tid < TM)
            atomicAdd(&rsumg[(size_t)blockIdx.z * HWDIM + bm + tid], rs[tid]);
    }
}

// ---------------- weight f32 -> bf16 + bias packing --------------------------
__global__ __launch_bounds__(256) void convert_w(const float* __restrict__ W0,
                                                 const float* __restrict__ W1,
                                                 const float* __restrict__ W2,
                                                 const float* __restrict__ W3,
                                                 bf16* __restrict__ out,
                                                 const float* __restrict__ b0,
                                                 const float* __restrict__ b1,
                                                 const float* __restrict__ b2,
                                                 float* __restrict__ bp) {
    int i = blockIdx.x * 256 + threadIdx.x;
    const int WN = CDIM * CDIM;
    int sel = i / WN, r = i % WN;
    const float* W = (sel == 0) ? W0 : (sel == 1) ? W1 : (sel == 2) ? W2 : W3;
    out[i] = __float2bfloat16(W[r]);
    if (i < 3 * CDIM) {
        int bs = i / CDIM, br = i % CDIM;
        const float* b = (bs == 0) ? b0 : (bs == 1) ? b1 : b2;
        bp[i] = b[br];
    }
}

// ---------------- GroupNorm, single global read via smem bf16 cache ---------
// Also zeroes the rowsum buffer (256 blocks x 128 floats = 32768).
__global__ __launch_bounds__(512) void gn_kernel(const float* __restrict__ x,
                                                 const float* __restrict__ gamma,
                                                 const float* __restrict__ beta,
                                                 bf16* __restrict__ xn,
                                                 float* __restrict__ rowsum) {
    extern __shared__ bf16 cache[];                // 128KB: CPG*HWDIM bf16
    __shared__ float rsum[512], rsum2[512];
    int b = blockIdx.x >> 5;
    int g = blockIdx.x & 31;
    int tid = threadIdx.x;
    const float* xp = x + ((size_t)b * CDIM + (size_t)g * CPG) * HWDIM;
    const int NEL = CPG * HWDIM;  // 65536

    if (tid < 128) rowsum[blockIdx.x * 128 + tid] = 0.f;

    float s = 0.f, s2 = 0.f;
    for (int i = tid * 4; i < NEL; i += 512 * 4) {
        float4 v = *(const float4*)(xp + i);
        cache[i + 0] = __float2bfloat16(v.x);
        cache[i + 1] = __float2bfloat16(v.y);
        cache[i + 2] = __float2bfloat16(v.z);
        cache[i + 3] = __float2bfloat16(v.w);
        s += v.x + v.y + v.z + v.w;
        s2 += v.x * v.x + v.y * v.y + v.z * v.z + v.w * v.w;
    }
    rsum[tid] = s; rsum2[tid] = s2;
    __syncthreads();
    for (int st = 256; st > 0; st >>= 1) {
        if (tid < st) { rsum[tid] += rsum[tid + st];
                        rsum2[tid] += rsum2[tid + st]; }
        __syncthreads();
    }
    float mean = rsum[0] * (1.f / NEL);
    float var  = rsum2[0] * (1.f / NEL) - mean * mean;
    float rstd = rsqrtf(var + EPSV);

    for (int i = tid; i < NEL; i += 512) {
        int c  = i & (CPG - 1);
        int hw = i >> 4;
        int cg = g * CPG + c;
        float v = __bfloat162float(cache[(size_t)c * HWDIM + hw]);
        xn[((size_t)b * HWDIM + hw) * CDIM + cg] =
            __float2bfloat16((v - mean) * rstd * gamma[cg] + beta[cg]);
    }
}

// ---------------- launch ----------------------------------------------------
extern "C" void kernel_launch(void* const* d_in, const int* in_sizes, int n_in,
                              void* d_out, int out_size) {
    const float* x     = (const float*)d_in[0];
    const float* gamma = (const float*)d_in[1];
    const float* beta  = (const float*)d_in[2];
    const float* Wq    = (const float*)d_in[3];
    const float* bq    = (const float*)d_in[4];
    const float* Wk    = (const float*)d_in[5];
    const float* bk    = (const float*)d_in[6];
    const float* Wv    = (const float*)d_in[7];
    const float* bv    = (const float*)d_in[8];
    const float* Wo    = (const float*)d_in[9];
    float* out = (float*)d_out;

    bf16 *xnb, *qkb, *vtb, *sb, *attnb, *wb;
    float *biasp, *rowsum;
    cudaGetSymbolAddress((void**)&xnb,    g_xnb);
    cudaGetSymbolAddress((void**)&qkb,    g_qkb);
    cudaGetSymbolAddress((void**)&vtb,    g_vtb);
    cudaGetSymbolAddress((void**)&sb,     g_sb);
    cudaGetSymbolAddress((void**)&attnb,  g_attnb);
    cudaGetSymbolAddress((void**)&wb,     g_wb);
    cudaGetSymbolAddress((void**)&biasp,  g_biasp);
    cudaGetSymbolAddress((void**)&rowsum, g_rowsum);

    static bool attr_set = false;
    if (!attr_set) {
        cudaFuncSetAttribute(gemm_bf16, cudaFuncAttributeMaxDynamicSharedMemorySize, SMEM_DYN);
        cudaFuncSetAttribute(gn_kernel, cudaFuncAttributeMaxDynamicSharedMemorySize, GN_SMEM);
        attr_set = true;
    }

    const int M_all = BATCH * HWDIM;
    const size_t strQ = (size_t)HWDIM * CDIM;
    const size_t strS = (size_t)HWDIM * HWDIM;
    const int WN = CDIM * CDIM;
    const float inv_sqrt_c = 0.044194173824159216f;

    bf16* qb = qkb;
    bf16* kb = qkb + (size_t)M_all * CDIM;
    bf16* wvb = wb + 2 * WN;
    bf16* wob = wb + 3 * WN;

    // 0. weights -> bf16, biases packed
    convert_w<<<4 * WN / 256, 256>>>(Wq, Wk, Wv, Wo, wb, bq, bk, bv, biasp);

    // 1. GroupNorm -> bf16 [B,N,C]; also zeroes rowsum
    gn_kernel<<<BATCH * 32, 512, GN_SMEM>>>(x, gamma, beta, xnb, rowsum);

    // 2a. Q,K projections (one launch, z in {0,1})
    dim3 gqk(CDIM / TN, M_all / TM, 2);
    gemm_bf16<<<gqk, 256, SMEM_DYN>>>(xnb, wb, biasp, qkb, nullptr, nullptr,
                                      CDIM, CDIM, CDIM, CDIM, 1.f, 1,
                                      0, (size_t)WN, (size_t)M_all * CDIM, CDIM);

    // 2b. V^T directly: Vt = Wv @ xn^T  -> [B][C][token] planes (mode 3)
    dim3 gvt(M_all / TN, CDIM / TM, 1);
    gemm_bf16<<<gvt, 256, SMEM_DYN>>>(wvb, xnb, biasp + 2 * CDIM, vtb, nullptr, nullptr,
                                      CDIM, CDIM, CDIM, 0, 1.f, 3, 0, 0, 0, 0);

    // 3. P = exp(Q @ K^T / sqrt(C)) with fused row-sum accumulation (mode 5)
    dim3 gs(HWDIM / TN, HWDIM / TM, BATCH);
    gemm_bf16<<<gs, 256, SMEM_DYN>>>(qb, kb, nullptr, sb, nullptr, rowsum,
                                     CDIM, CDIM, CDIM, HWDIM,
                                     inv_sqrt_c, 5, strQ, strQ, strS, 0);

    // 4. A = (P @ Vt^T) / rowsum  (mode 6)
    dim3 gpv(CDIM / TN, HWDIM / TM, BATCH);
    gemm_bf16<<<gpv, 256, SMEM_DYN>>>(sb, vtb, nullptr, attnb, nullptr, rowsum,
                                      HWDIM, HWDIM, HWDIM, CDIM,
                                      1.f, 6, strS, strQ, strQ, 0);

    // 5. O = A @ Wo^T fused with residual + transpose to [B,C,H,W]
    dim3 gproj(CDIM / TN, M_all / TM, 1);
    gemm_bf16<<<gproj, 256, SMEM_DYN>>>(attnb, wob, nullptr, out, x, nullptr,
                                        CDIM, CDIM, CDIM, CDIM, 1.f, 2, 0, 0, 0, 0);
}

// round 16
// speedup vs baseline: 1.5852x; 1.5852x over previous
#include <cuda_runtime.h>
#include <cuda_bf16.h>
#include <math.h>
#include <stdint.h>

// Shapes (fixed)
#define BATCH 8
#define CDIM 512
#define HWDIM 4096
#define CPG 16
#define EPSV 1e-6f

// GEMM tiling: 128x128 CTA tile, BK=64 bf16 (128B rows), 3-stage cp.async
#define TM 128
#define TN 128
#define BK 64
#define TILE_BYTES (TM * 128)           // 16KB per operand stage
#define STG_BYTES (2 * TILE_BYTES)      // 32KB
#define NSTAGE 3
#define SMEM_DYN (NSTAGE * STG_BYTES)   // 96KB

typedef __nv_bfloat16 bf16;
typedef __nv_bfloat162 bf162;

// ---------------- scratch (device globals) ---------------------------------
__device__ bf16  g_xnb [(size_t)BATCH * HWDIM * CDIM];     // 32MB GN out [B,N,C]
__device__ bf16  g_qkb [(size_t)2 * BATCH * HWDIM * CDIM]; // 64MB Q,K planes
__device__ bf16  g_vtb [(size_t)BATCH * HWDIM * CDIM];     // 32MB V^T [B,C,N]
__device__ bf16  g_sb  [(size_t)BATCH * HWDIM * HWDIM];    // 256MB exp-scores bf16
__device__ bf16  g_attnb[(size_t)BATCH * HWDIM * CDIM];    // 32MB P@V out
__device__ bf16  g_wb  [4 * CDIM * CDIM];                  // 2MB bf16 weights
__device__ float g_biasp[3 * CDIM];                        // packed biases q,k,v
__device__ float g_rowsum[BATCH * HWDIM];                  // softmax denominators
__device__ float g_stats[2 * BATCH * 32];                  // GN sums (s, s2) per group

// ---------------- PTX helpers ----------------------------------------------
__device__ __forceinline__ uint32_t smem_u32(const void* p) {
    uint32_t a;
    asm("{ .reg .u64 t; cvta.to.shared.u64 t, %1; cvt.u32.u64 %0, t; }"
        : "=r"(a) : "l"(p));
    return a;
}

__device__ __forceinline__ void ldsm4(uint32_t* r, uint32_t addr) {
    asm volatile("ldmatrix.sync.aligned.m8n8.x4.shared.b16 {%0,%1,%2,%3}, [%4];"
                 : "=r"(r[0]), "=r"(r[1]), "=r"(r[2]), "=r"(r[3]) : "r"(addr));
}

__device__ __forceinline__ void mma_bf16(float* c, const uint32_t* a,
                                         uint32_t b0, uint32_t b1) {
    asm volatile(
        "mma.sync.aligned.m16n8k16.row.col.f32.bf16.bf16.f32 "
        "{%0,%1,%2,%3}, {%4,%5,%6,%7}, {%8,%9}, {%0,%1,%2,%3};"
        : "+f"(c[0]), "+f"(c[1]), "+f"(c[2]), "+f"(c[3])
        : "r"(a[0]), "r"(a[1]), "r"(a[2]), "r"(a[3]), "r"(b0), "r"(b1));
}

__device__ __forceinline__ void cp16(uint32_t dst, const void* src) {
    asm volatile("cp.async.cg.shared.global [%0], [%1], 16;" :: "r"(dst), "l"(src));
}
#define CP_COMMIT() asm volatile("cp.async.commit_group;" ::: "memory")
#define CP_WAIT1()  asm volatile("cp.async.wait_group 1;" ::: "memory")

// ---------------- bf16 GEMM NT: C = alpha * A @ B^T (+ bias) ----------------
// A: [M,K] lda, B: [N,K] ldb bf16 K-major.
// mode 0: f32 C row-major
// mode 1: bf16 C row-major (per-z plane sC; bias per-z plane sBias, col-index)
// mode 2: fused residual + transpose -> f32 [B,C,H,W]
// mode 3: V^T planes: C[(n>>12)*HW*C + m*HW + (n&4095)], bias row-indexed
// mode 5: S-GEMM: store bf16(exp(acc*alpha)); accumulate row sums -> rsumg
// mode 6: PV: bf16 out scaled by 1/rsumg[z*HW + m]
__global__ __launch_bounds__(256, 2) void gemm_bf16(const bf16* __restrict__ A,
                                                    const bf16* __restrict__ B,
                                                    const float* __restrict__ bias,
                                                    void* __restrict__ Cv,
                                                    const float* __restrict__ xres,
                                                    float* __restrict__ rsumg,
                                                    int K, int lda, int ldb, int ldc,
                                                    float alpha, int mode,
                                                    size_t sA, size_t sB, size_t sC,
                                                    int sBias) {
    extern __shared__ char dsm[];
    uint32_t smem_base = smem_u32(dsm);

    A += (size_t)blockIdx.z * sA;
    B += (size_t)blockIdx.z * sB;
    if (bias) bias += (size_t)blockIdx.z * sBias;
    int bm = blockIdx.y * TM, bn = blockIdx.x * TN;
    int tid = threadIdx.x, wid = tid >> 5, lane = tid & 31;
    int wm = (wid & 1) * 64, wn = (wid >> 1) * 32;

    int lrow = tid >> 1;
    int g0 = (tid & 1) * 4;
    const bf16* ag = A + (size_t)(bm + lrow) * lda + g0 * 8;
    const bf16* bg = B + (size_t)(bn + lrow) * ldb + g0 * 8;
    int rx = lrow & 7;
    uint32_t sAoff[4], sBoff[4];
    #pragma unroll
    for (int j = 0; j < 4; j++) {
        uint32_t o = (uint32_t)lrow * 128 + (uint32_t)(((g0 + j) ^ rx) << 4);
        sAoff[j] = o;
        sBoff[j] = TILE_BYTES + o;
    }

    int arl = (lane & 7) + ((lane >> 3) & 1) * 8;
    int ahi = lane >> 4;
    uint32_t a_rowoff[4]; int a_rx[4];
    #pragma unroll
    for (int mf = 0; mf < 4; mf++) {
        int row = wm + mf * 16 + arl;
        a_rowoff[mf] = (uint32_t)row * 128;
        a_rx[mf] = row & 7;
    }
    int brl = (lane & 7) + ((lane >> 4) & 1) * 8;
    int bhi = (lane >> 3) & 1;
    uint32_t b_rowoff[2]; int b_rx[2];
    #pragma unroll
    for (int ng = 0; ng < 2; ng++) {
        int row = wn + ng * 16 + brl;
        b_rowoff[ng] = TILE_BYTES + (uint32_t)row * 128;
        b_rx[ng] = row & 7;
    }

    const int NC = K / BK;

    #pragma unroll
    for (int c = 0; c < 2; c++) {
        uint32_t st = smem_base + c * STG_BYTES;
        const bf16* a0 = ag + c * BK;
        const bf16* b0 = bg + c * BK;
        #pragma unroll
        for (int j = 0; j < 4; j++) cp16(st + sAoff[j], a0 + j * 8);
        #pragma unroll
        for (int j = 0; j < 4; j++) cp16(st + sBoff[j], b0 + j * 8);
        CP_COMMIT();
    }

    float acc[4][4][4];
    #pragma unroll
    for (int i = 0; i < 4; i++)
        #pragma unroll
        for (int j = 0; j < 4; j++)
            #pragma unroll
            for (int r = 0; r < 4; r++) acc[i][j][r] = 0.f;

    for (int c = 0; c < NC; c++) {
        int buf = c % NSTAGE;
        CP_WAIT1();
        __syncthreads();
        if (c + 2 < NC) {
            uint32_t st = smem_base + ((c + 2) % NSTAGE) * STG_BYTES;
            const bf16* a0 = ag + (c + 2) * BK;
            const bf16* b0 = bg + (c + 2) * BK;
            #pragma unroll
            for (int j = 0; j < 4; j++) cp16(st + sAoff[j], a0 + j * 8);
            #pragma unroll
            for (int j = 0; j < 4; j++) cp16(st + sBoff[j], b0 + j * 8);
        }
        CP_COMMIT();

        uint32_t base = smem_base + buf * STG_BYTES;
        #pragma unroll
        for (int kf = 0; kf < 4; kf++) {
            uint32_t a[4][4], b[2][4];
            #pragma unroll
            for (int mf = 0; mf < 4; mf++)
                ldsm4(a[mf], base + a_rowoff[mf] +
                      (uint32_t)(((((kf << 1) | ahi)) ^ a_rx[mf]) << 4));
            #pragma unroll
            for (int ng = 0; ng < 2; ng++)
                ldsm4(b[ng], base + b_rowoff[ng] +
                      (uint32_t)(((((kf << 1) | bhi)) ^ b_rx[ng]) << 4));
            #pragma unroll
            for (int mf = 0; mf < 4; mf++)
                #pragma unroll
                for (int ng = 0; ng < 2; ng++) {
                    mma_bf16(acc[mf][ng * 2 + 0], a[mf], b[ng][0], b[ng][1]);
                    mma_bf16(acc[mf][ng * 2 + 1], a[mf], b[ng][2], b[ng][3]);
                }
        }
    }
    __syncthreads();

    // ---- epilogue ----
    float* rs = (float*)dsm;             // smem reused for row sums (mode 5)
    if (mode == 5) {
        if (tid < TM) rs[tid] = 0.f;
        __syncthreads();
    }

    int r4 = lane >> 2, c2 = (lane & 3) * 2;
    #pragma unroll
    for (int mf = 0; mf < 4; mf++) {
        int lr = wm + mf * 16 + r4;          // local row in tile
        int m0 = bm + lr;
        float inv0 = 1.f, inv1 = 1.f;
        if (mode == 6) {
            inv0 = 1.f / rsumg[(size_t)blockIdx.z * HWDIM + m0];
            inv1 = 1.f / rsumg[(size_t)blockIdx.z * HWDIM + m0 + 8];
        }
        float p0 = 0.f, p1 = 0.f;            // row-sum partials (mode 5)
        #pragma unroll
        for (int nf = 0; nf < 4; nf++) {
            int n0 = bn + wn + (nf >> 1) * 16 + (nf & 1) * 8 + c2;
            float bx = 0.f, by = 0.f;
            if (bias && mode != 3) { bx = bias[n0]; by = bias[n0 + 1]; }
            float* ac = acc[mf][nf];
            float x0 = ac[0] * alpha + bx, y0 = ac[1] * alpha + by;
            float x1 = ac[2] * alpha + bx, y1 = ac[3] * alpha + by;
            if (mode == 1) {
                bf16* C = (bf16*)Cv + blockIdx.z * sC;
                bf162 h0 = __floats2bfloat162_rn(x0, y0);
                bf162 h1 = __floats2bfloat162_rn(x1, y1);
                *(bf162*)(C + (size_t)m0 * ldc + n0) = h0;
                *(bf162*)(C + (size_t)(m0 + 8) * ldc + n0) = h1;
            } else if (mode == 5) {
                x0 = __expf(x0); y0 = __expf(y0);
                x1 = __expf(x1); y1 = __expf(y1);
                p0 += x0 + y0;  p1 += x1 + y1;
                bf16* C = (bf16*)Cv + blockIdx.z * sC;
                bf162 h0 = __floats2bfloat162_rn(x0, y0);
                bf162 h1 = __floats2bfloat162_rn(x1, y1);
                *(bf162*)(C + (size_t)m0 * ldc + n0) = h0;
                *(bf162*)(C + (size_t)(m0 + 8) * ldc + n0) = h1;
            } else if (mode == 6) {
                bf16* C = (bf16*)Cv + blockIdx.z * sC;
                bf162 h0 = __floats2bfloat162_rn(x0 * inv0, y0 * inv0);
                bf162 h1 = __floats2bfloat162_rn(x1 * inv1, y1 * inv1);
                *(bf162*)(C + (size_t)m0 * ldc + n0) = h0;
                *(bf162*)(C + (size_t)(m0 + 8) * ldc + n0) = h1;
            } else if (mode == 0) {
                float* C = (float*)Cv + blockIdx.z * sC;
                *(float2*)(C + (size_t)m0 * ldc + n0) = make_float2(x0, y0);
                *(float2*)(C + (size_t)(m0 + 8) * ldc + n0) = make_float2(x1, y1);
            } else if (mode == 2) {
                float* C = (float*)Cv;
                int m1 = m0 + 8;
                size_t i00 = (((size_t)(m0 >> 12) * CDIM) + n0) * HWDIM + (m0 & 4095);
                size_t i01 = (((size_t)(m0 >> 12) * CDIM) + n0 + 1) * HWDIM + (m0 & 4095);
                size_t i10 = (((size_t)(m1 >> 12) * CDIM) + n0) * HWDIM + (m1 & 4095);
                size_t i11 = (((size_t)(m1 >> 12) * CDIM) + n0 + 1) * HWDIM + (m1 & 4095);
                C[i00] = x0 + xres[i00];
                C[i01] = y0 + xres[i01];
                C[i10] = x1 + xres[i10];
                C[i11] = y1 + xres[i11];
            } else {
                // mode 3: V^T planes; m = channel, n = global token; bias by row
                bf16* C = (bf16*)Cv;
                float b0f = bias ? bias[m0] : 0.f;
                float b1f = bias ? bias[m0 + 8] : 0.f;
                bf162 h0 = __floats2bfloat162_rn(x0 + b0f, y0 + b0f);
                bf162 h1 = __floats2bfloat162_rn(x1 + b1f, y1 + b1f);
                size_t plane = (size_t)(n0 >> 12) * ((size_t)HWDIM * CDIM);
                int nt = n0 & 4095;
                *(bf162*)(C + plane + (size_t)m0 * HWDIM + nt) = h0;
                *(bf162*)(C + plane + (size_t)(m0 + 8) * HWDIM + nt) = h1;
            }
        }
        if (mode == 5) {
            atomicAdd(&rs[lr], p0);
            atomicAdd(&rs[lr + 8], p1);
        }
    }
    if (mode == 5) {
        __syncthreads();
        if (tid < TM)
            atomicAdd(&rsumg[(size_t)blockIdx.z * HWDIM + bm + tid], rs[tid]);
    }
}

// ---------------- weight f32 -> bf16 + bias pack + zero stats/rowsum --------
__global__ __launch_bounds__(256) void convert_w(const float* __restrict__ W0,
                                                 const float* __restrict__ W1,
                                                 const float* __restrict__ W2,
                                                 const float* __restrict__ W3,
                                                 bf16* __restrict__ out,
                                                 const float* __restrict__ b0,
                                                 const float* __restrict__ b1,
                                                 const float* __restrict__ b2,
                                                 float* __restrict__ bp,
                                                 float* __restrict__ stats,
                                                 float* __restrict__ rowsum) {
    int i = blockIdx.x * 256 + threadIdx.x;
    const int WN = CDIM * CDIM;
    int sel = i / WN, r = i % WN;
    const float* W = (sel == 0) ? W0 : (sel == 1) ? W1 : (sel == 2) ? W2 : W3;
    out[i] = __float2bfloat16(W[r]);
    if (i < 3 * CDIM) {
        int bs = i / CDIM, br = i % CDIM;
        const float* b = (bs == 0) ? b0 : (bs == 1) ? b1 : b2;
        bp[i] = b[br];
    }
    if (i < 2 * BATCH * 32) stats[i] = 0.f;
    if (i < BATCH * HWDIM) rowsum[i] = 0.f;
}

// ---------------- GN pass 1: partial sums per (group, chunk) ----------------
// grid: (256 groups, 8 chunks), 256 threads; each block sums 8192 elems.
__global__ __launch_bounds__(256) void gn_stats(const float* __restrict__ x,
                                                float* __restrict__ stats) {
    __shared__ float rs[256], rs2[256];
    int gid = blockIdx.x;
    const float* xp = x + (size_t)gid * CPG * HWDIM + blockIdx.y * 8192;
    int tid = threadIdx.x;

    float s = 0.f, s2 = 0.f;
    #pragma unroll
    for (int i = 0; i < 8; i++) {
        float4 v = *(const float4*)(xp + tid * 4 + i * 1024);
        s += v.x + v.y + v.z + v.w;
        s2 += v.x * v.x + v.y * v.y + v.z * v.z + v.w * v.w;
    }
    rs[tid] = s; rs2[tid] = s2;
    __syncthreads();
    for (int st = 128; st > 0; st >>= 1) {
        if (tid < st) { rs[tid] += rs[tid + st]; rs2[tid] += rs2[tid + st]; }
        __syncthreads();
    }
    if (tid == 0) {
        atomicAdd(&stats[gid * 2 + 0], rs[0]);
        atomicAdd(&stats[gid * 2 + 1], rs2[0]);
    }
}

// ---------------- GN pass 2: normalize -> bf16 [B,N,C] ----------------------
// grid: (256 groups, 8 hw-chunks of 512), 256 threads; thread handles 2 hw x 16 c.
__global__ __launch_bounds__(256) void gn_norm(const float* __restrict__ x,
                                               const float* __restrict__ gamma,
                                               const float* __restrict__ beta,
                                               const float* __restrict__ stats,
                                               bf16* __restrict__ xn) {
    int gid = blockIdx.x;
    int b = gid >> 5, g = gid & 31;
    const float* xp = x + (size_t)gid * CPG * HWDIM;
    const int NEL = CPG * HWDIM;

    float s = stats[gid * 2 + 0], s2 = stats[gid * 2 + 1];
    float mean = s * (1.f / NEL);
    float var  = s2 * (1.f / NEL) - mean * mean;
    float rstd = rsqrtf(var + EPSV);

    __shared__ float sg[CPG], sbta[CPG];
    if (threadIdx.x < CPG) {
        sg[threadIdx.x]   = gamma[g * CPG + threadIdx.x] * rstd;
        sbta[threadIdx.x] = beta[g * CPG + threadIdx.x];
    }
    __syncthreads();

    #pragma unroll
    for (int h = 0; h < 2; h++) {
        int hw = blockIdx.y * 512 + threadIdx.x + h * 256;
        bf16 tmp[CPG];
        #pragma unroll
        for (int c = 0; c < CPG; c++) {
            float v = xp[(size_t)c * HWDIM + hw];
            tmp[c] = __float2bfloat16((v - mean) * sg[c] + sbta[c]);
        }
        *(uint4*)(xn + ((size_t)b * HWDIM + hw) * CDIM + g * CPG) = *(uint4*)&tmp[0];
        *(uint4*)(xn + ((size_t)b * HWDIM + hw) * CDIM + g * CPG + 8) = *(uint4*)&tmp[8];
    }
}

// ---------------- launch ----------------------------------------------------
extern "C" void kernel_launch(void* const* d_in, const int* in_sizes, int n_in,
                              void* d_out, int out_size) {
    const float* x     = (const float*)d_in[0];
    const float* gamma = (const float*)d_in[1];
    const float* beta  = (const float*)d_in[2];
    const float* Wq    = (const float*)d_in[3];
    const float* bq    = (const float*)d_in[4];
    const float* Wk    = (const float*)d_in[5];
    const float* bk    = (const float*)d_in[6];
    const float* Wv    = (const float*)d_in[7];
    const float* bv    = (const float*)d_in[8];
    const float* Wo    = (const float*)d_in[9];
    float* out = (float*)d_out;

    bf16 *xnb, *qkb, *vtb, *sb, *attnb, *wb;
    float *biasp, *rowsum, *stats;
    cudaGetSymbolAddress((void**)&xnb,    g_xnb);
    cudaGetSymbolAddress((void**)&qkb,    g_qkb);
    cudaGetSymbolAddress((void**)&vtb,    g_vtb);
    cudaGetSymbolAddress((void**)&sb,     g_sb);
    cudaGetSymbolAddress((void**)&attnb,  g_attnb);
    cudaGetSymbolAddress((void**)&wb,     g_wb);
    cudaGetSymbolAddress((void**)&biasp,  g_biasp);
    cudaGetSymbolAddress((void**)&rowsum, g_rowsum);
    cudaGetSymbolAddress((void**)&stats,  g_stats);

    static bool attr_set = false;
    if (!attr_set) {
        cudaFuncSetAttribute(gemm_bf16, cudaFuncAttributeMaxDynamicSharedMemorySize, SMEM_DYN);
        attr_set = true;
    }

    const int M_all = BATCH * HWDIM;
    const size_t strQ = (size_t)HWDIM * CDIM;
    const size_t strS = (size_t)HWDIM * HWDIM;
    const int WN = CDIM * CDIM;
    const float inv_sqrt_c = 0.044194173824159216f;

    bf16* qb = qkb;
    bf16* kb = qkb + (size_t)M_all * CDIM;
    bf16* wvb = wb + 2 * WN;
    bf16* wob = wb + 3 * WN;

    // 0. weights -> bf16, biases packed, stats+rowsum zeroed
    convert_w<<<4 * WN / 256, 256>>>(Wq, Wk, Wv, Wo, wb, bq, bk, bv, biasp,
                                     stats, rowsum);

    // 1. GroupNorm: full-chip two-pass
    dim3 ggn(BATCH * 32, 8, 1);
    gn_stats<<<ggn, 256>>>(x, stats);
    gn_norm<<<ggn, 256>>>(x, gamma, beta, stats, xnb);

    // 2a. Q,K projections (one launch, z in {0,1})
    dim3 gqk(CDIM / TN, M_all / TM, 2);
    gemm_bf16<<<gqk, 256, SMEM_DYN>>>(xnb, wb, biasp, qkb, nullptr, nullptr,
                                      CDIM, CDIM, CDIM, CDIM, 1.f, 1,
                                      0, (size_t)WN, (size_t)M_all * CDIM, CDIM);

    // 2b. V^T directly: Vt = Wv @ xn^T  -> [B][C][token] planes (mode 3)
    dim3 gvt(M_all / TN, CDIM / TM, 1);
    gemm_bf16<<<gvt, 256, SMEM_DYN>>>(wvb, xnb, biasp + 2 * CDIM, vtb, nullptr, nullptr,
                                      CDIM, CDIM, CDIM, 0, 1.f, 3, 0, 0, 0, 0);

    // 3. P = exp(Q @ K^T / sqrt(C)) with fused row-sum accumulation (mode 5)
    dim3 gs(HWDIM / TN, HWDIM / TM, BATCH);
    gemm_bf16<<<gs, 256, SMEM_DYN>>>(qb, kb, nullptr, sb, nullptr, rowsum,
                                     CDIM, CDIM, CDIM, HWDIM,
                                     inv_sqrt_c, 5, strQ, strQ, strS, 0);

    // 4. A = (P @ Vt^T) / rowsum  (mode 6)
    dim3 gpv(CDIM / TN, HWDIM / TM, BATCH);
    gemm_bf16<<<gpv, 256, SMEM_DYN>>>(sb, vtb, nullptr, attnb, nullptr, rowsum,
                                      HWDIM, HWDIM, HWDIM, CDIM,
                                      1.f, 6, strS, strQ, strQ, 0);

    // 5. O = A @ Wo^T fused with residual + transpose to [B,C,H,W]
    dim3 gproj(CDIM / TN, M_all / TM, 1);
    gemm_bf16<<<gproj, 256, SMEM_DYN>>>(attnb, wob, nullptr, out, x, nullptr,
                                        CDIM, CDIM, CDIM, CDIM, 1.f, 2, 0, 0, 0, 0);
}